// round 14
// baseline (speedup 1.0000x reference)
#include <cuda_runtime.h>
#include <cuda_bf16.h>
#include <cstdint>

// ---------------- problem constants ----------------
#define NN   50000
#define EE   600000
#define HD   256
#define NG   64
#define SCAN_B 1024
#define NBLK ((NN + SCAN_B - 1) / SCAN_B)   // 49
#define MTILES ((NN + 127) / 128)           // 391

// ---------------- device scratch -------------------
__device__ float g_bufA[NN * HD];
__device__ float g_bufB[NN * HD];
__device__ __nv_bfloat16 g_ahi[NN * HD];       // GEMM A operand, hi
__device__ __nv_bfloat16 g_alo[NN * HD];       // GEMM A operand, lo
__device__ __nv_bfloat16 g_wthi[3 * HD * HD];  // W^T split hi [layer][n][k]
__device__ __nv_bfloat16 g_wtlo[3 * HD * HD];  // W^T split lo
__device__ float g_dinv[NN];
__device__ int   g_rowptr[NN + 1];
__device__ int   g_cnt[NN];
__device__ int   g_fill[NN];
__device__ int2  g_edge[EE];                   // packed (col, val-as-int)
__device__ int   g_gstart[NG + 1];
__device__ int   g_bsum[64];
__device__ float g_poolp[NG * 8 * HD];         // partial pools

// ---------------- small helpers ----------------
__device__ __forceinline__ uint32_t smem_u32(const void* p) {
    uint32_t a;
    asm("{ .reg .u64 t; cvta.to.shared.u64 t, %1; cvt.u32.u64 %0, t; }"
        : "=r"(a) : "l"(p));
    return a;
}
__device__ __forceinline__ void cp_async16(uint32_t dst, const void* src) {
    asm volatile("cp.async.cg.shared.global [%0], [%1], 16;"
                 :: "r"(dst), "l"(src));
}
#define CP_COMMIT() asm volatile("cp.async.commit_group;")
#define CP_WAIT(n)  asm volatile("cp.async.wait_group %0;" :: "n"(n))

__device__ __forceinline__ void ldsm_x4(uint32_t* r, uint32_t addr) {
    asm volatile("ldmatrix.sync.aligned.m8n8.x4.shared.b16 {%0,%1,%2,%3}, [%4];"
                 : "=r"(r[0]), "=r"(r[1]), "=r"(r[2]), "=r"(r[3]) : "r"(addr));
}
__device__ __forceinline__ void mma_bf16(float* c, const uint32_t* a,
                                         uint32_t b0, uint32_t b1) {
    asm volatile(
        "mma.sync.aligned.m16n8k16.row.col.f32.bf16.bf16.f32 "
        "{%0,%1,%2,%3}, {%4,%5,%6,%7}, {%8,%9}, {%0,%1,%2,%3};"
        : "+f"(c[0]), "+f"(c[1]), "+f"(c[2]), "+f"(c[3])
        : "r"(a[0]), "r"(a[1]), "r"(a[2]), "r"(a[3]), "r"(b0), "r"(b1));
}
__device__ __forceinline__ void split_bf16(float v, __nv_bfloat16& hi, __nv_bfloat16& lo) {
    hi = __float2bfloat16(v);
    lo = __float2bfloat16(v - __bfloat162float(hi));
}

// ---------------- setup kernels ----------------
__global__ void count_kernel(const int* __restrict__ ei, const int* __restrict__ batch) {
    int e = blockIdx.x * blockDim.x + threadIdx.x;
    if (e < EE) {
        int d = ei[EE + e];
        atomicAdd(&g_cnt[d], 1);
        atomicAdd(&g_bsum[d >> 10], 1);
    }
    if (blockIdx.x == 0 && threadIdx.x <= NG) {
        int g = threadIdx.x;
        int lo = 0, hi = NN;
        while (lo < hi) { int m = (lo + hi) >> 1; if (batch[m] < g) lo = m + 1; else hi = m; }
        g_gstart[g] = lo;
    }
}
__global__ void scan_kernel() {
    __shared__ int sh[SCAN_B];
    __shared__ int sb[64];
    __shared__ int spref;
    int b = blockIdx.x, t = threadIdx.x;
    if (t < 64) sb[t] = (t < NBLK) ? g_bsum[t] : 0;
    __syncthreads();
    if (t == 0) {
        int s = 0;
        for (int i = 0; i < b; i++) s += sb[i];
        spref = s;
    }
    int i = b * SCAN_B + t;
    int c = (i < NN) ? g_cnt[i] : 0;
    if (i < NN) g_dinv[i] = rsqrtf((float)(c + 1));
    sh[t] = c;
    __syncthreads();
    #pragma unroll
    for (int off = 1; off < SCAN_B; off <<= 1) {
        int x = (t >= off) ? sh[t - off] : 0;
        __syncthreads();
        sh[t] += x;
        __syncthreads();
    }
    if (i < NN) g_rowptr[i + 1] = sh[t] + spref;
    if (b == 0 && t == 0) g_rowptr[0] = 0;
}
__global__ void fill_kernel(const int* __restrict__ ei) {
    int e = blockIdx.x * blockDim.x + threadIdx.x;
    if (e < EE) {
        int s = ei[e], d = ei[EE + e];
        int p = g_rowptr[d] + atomicAdd(&g_fill[d], 1);
        g_edge[p] = make_int2(s, __float_as_int(g_dinv[s]));
    }
}
__global__ void convert_w_kernel(const float* __restrict__ W0,
                                 const float* __restrict__ W1,
                                 const float* __restrict__ W2) {
    int i = blockIdx.x * blockDim.x + threadIdx.x;
    if (i >= 3 * HD * HD) return;
    int layer = i / (HD * HD), r = i % (HD * HD);
    int n = r / HD, k = r % HD;
    const float* W = (layer == 0) ? W0 : (layer == 1) ? W1 : W2;
    __nv_bfloat16 h, l; split_bf16(W[k * HD + n], h, l);   // Wt[n][k] = W[k][n]
    g_wthi[i] = h; g_wtlo[i] = l;
}
__global__ void convert_x_kernel(const float* __restrict__ x) {
    int i = (blockIdx.x * blockDim.x + threadIdx.x) * 4;
    if (i >= NN * HD) return;
    float4 v = *(const float4*)&x[i];
    __nv_bfloat16 h0, l0, h1, l1, h2, l2, h3, l3;
    split_bf16(v.x, h0, l0); split_bf16(v.y, h1, l1);
    split_bf16(v.z, h2, l2); split_bf16(v.w, h3, l3);
    g_ahi[i] = h0; g_ahi[i + 1] = h1; g_ahi[i + 2] = h2; g_ahi[i + 3] = h3;
    g_alo[i] = l0; g_alo[i + 1] = l1; g_alo[i + 2] = l2; g_alo[i + 3] = l3;
}

// ---------------- aggregation: g = D^-1/2 (A+I) D^-1/2 h ------------------
// warp per node, lane owns 8 features (2 x float4).
// BR: fuse +bias,relu.  BF16OUT: write bf16 hi/lo (GEMM operand) else f32.
template <bool BR, bool BF16OUT>
__global__ void __launch_bounds__(256)
agg_kernel(const float* __restrict__ h, const float* __restrict__ bias,
           float* __restrict__ g) {
    int node = blockIdx.x * 8 + (threadIdx.x >> 5);
    if (node >= NN) return;
    int lane = threadIdx.x & 31;
    int fb = lane * 8;
    float di = g_dinv[node];
    float4 a0, a1;
    {
        const float4* hp = (const float4*)&h[node * HD + fb];
        float4 v0 = hp[0], v1 = hp[1];
        a0 = make_float4(di * v0.x, di * v0.y, di * v0.z, di * v0.w);
        a1 = make_float4(di * v1.x, di * v1.y, di * v1.z, di * v1.w);
    }
    int beg = g_rowptr[node], end = g_rowptr[node + 1];
    int p = beg;
    for (; p + 4 <= end; p += 4) {
        int2 e0 = g_edge[p],     e1 = g_edge[p + 1];
        int2 e2 = g_edge[p + 2], e3 = g_edge[p + 3];
        float w0 = __int_as_float(e0.y), w1 = __int_as_float(e1.y);
        float w2 = __int_as_float(e2.y), w3 = __int_as_float(e3.y);
        const float4* h0 = (const float4*)&h[e0.x * HD + fb];
        const float4* h1 = (const float4*)&h[e1.x * HD + fb];
        const float4* h2 = (const float4*)&h[e2.x * HD + fb];
        const float4* h3 = (const float4*)&h[e3.x * HD + fb];
        float4 u00 = h0[0], u01 = h0[1];
        float4 u10 = h1[0], u11 = h1[1];
        float4 u20 = h2[0], u21 = h2[1];
        float4 u30 = h3[0], u31 = h3[1];
        a0.x = fmaf(w0, u00.x, a0.x); a0.y = fmaf(w0, u00.y, a0.y);
        a0.z = fmaf(w0, u00.z, a0.z); a0.w = fmaf(w0, u00.w, a0.w);
        a1.x = fmaf(w0, u01.x, a1.x); a1.y = fmaf(w0, u01.y, a1.y);
        a1.z = fmaf(w0, u01.z, a1.z); a1.w = fmaf(w0, u01.w, a1.w);
        a0.x = fmaf(w1, u10.x, a0.x); a0.y = fmaf(w1, u10.y, a0.y);
        a0.z = fmaf(w1, u10.z, a0.z); a0.w = fmaf(w1, u10.w, a0.w);
        a1.x = fmaf(w1, u11.x, a1.x); a1.y = fmaf(w1, u11.y, a1.y);
        a1.z = fmaf(w1, u11.z, a1.z); a1.w = fmaf(w1, u11.w, a1.w);
        a0.x = fmaf(w2, u20.x, a0.x); a0.y = fmaf(w2, u20.y, a0.y);
        a0.z = fmaf(w2, u20.z, a0.z); a0.w = fmaf(w2, u20.w, a0.w);
        a1.x = fmaf(w2, u21.x, a1.x); a1.y = fmaf(w2, u21.y, a1.y);
        a1.z = fmaf(w2, u21.z, a1.z); a1.w = fmaf(w2, u21.w, a1.w);
        a0.x = fmaf(w3, u30.x, a0.x); a0.y = fmaf(w3, u30.y, a0.y);
        a0.z = fmaf(w3, u30.z, a0.z); a0.w = fmaf(w3, u30.w, a0.w);
        a1.x = fmaf(w3, u31.x, a1.x); a1.y = fmaf(w3, u31.y, a1.y);
        a1.z = fmaf(w3, u31.z, a1.z); a1.w = fmaf(w3, u31.w, a1.w);
    }
    for (; p < end; p++) {
        int2 e0 = g_edge[p];
        float w = __int_as_float(e0.y);
        const float4* hp = (const float4*)&h[e0.x * HD + fb];
        float4 u0 = hp[0], u1 = hp[1];
        a0.x = fmaf(w, u0.x, a0.x); a0.y = fmaf(w, u0.y, a0.y);
        a0.z = fmaf(w, u0.z, a0.z); a0.w = fmaf(w, u0.w, a0.w);
        a1.x = fmaf(w, u1.x, a1.x); a1.y = fmaf(w, u1.y, a1.y);
        a1.z = fmaf(w, u1.z, a1.z); a1.w = fmaf(w, u1.w, a1.w);
    }
    float4 r0 = make_float4(di * a0.x, di * a0.y, di * a0.z, di * a0.w);
    float4 r1 = make_float4(di * a1.x, di * a1.y, di * a1.z, di * a1.w);
    if (BR) {
        float4 b0v = *(const float4*)&bias[fb];
        float4 b1v = *(const float4*)&bias[fb + 4];
        r0 = make_float4(fmaxf(r0.x + b0v.x, 0.f), fmaxf(r0.y + b0v.y, 0.f),
                         fmaxf(r0.z + b0v.z, 0.f), fmaxf(r0.w + b0v.w, 0.f));
        r1 = make_float4(fmaxf(r1.x + b1v.x, 0.f), fmaxf(r1.y + b1v.y, 0.f),
                         fmaxf(r1.z + b1v.z, 0.f), fmaxf(r1.w + b1v.w, 0.f));
    }
    if (BF16OUT) {
        union { __nv_bfloat16 v[8]; uint4 u; } H, L;
        float fv[8] = { r0.x, r0.y, r0.z, r0.w, r1.x, r1.y, r1.z, r1.w };
        #pragma unroll
        for (int q = 0; q < 8; q++) split_bf16(fv[q], H.v[q], L.v[q]);
        *(uint4*)&g_ahi[node * HD + fb] = H.u;
        *(uint4*)&g_alo[node * HD + fb] = L.u;
    } else {
        float4* gp = (float4*)&g[node * HD + fb];
        gp[0] = r0;
        gp[1] = r1;
    }
}

// ---------------- mma.sync GEMM: C = [relu](A @ W [+ bias]) ---------------
// split-2 bf16, all four operand parts via cp.async, 2-stage double buffer.
// CTA 128x128, 8 warps; K chunks of 32. smem [row][40] bf16, plain ldmatrix.
#define TS    40
#define PART  (128 * TS * 2)          // 10240 B
#define CHUNK (4 * PART)              // Ahi,Alo,Bhi,Blo
#define GSMEM (2 * CHUNK)             // 81920 B

template <bool BR>
__global__ void __launch_bounds__(256, 2)
gemm_mma_kernel(const __nv_bfloat16* __restrict__ Ahi,
                const __nv_bfloat16* __restrict__ Alo,
                const __nv_bfloat16* __restrict__ Bhi,
                const __nv_bfloat16* __restrict__ Blo,
                const float* __restrict__ bias,
                float* __restrict__ C, int M) {
    extern __shared__ char smem[];
    uint32_t sb = smem_u32(smem);
    int tid = threadIdx.x, wid = tid >> 5, lid = tid & 31;
    int bm = blockIdx.x * 128, bn = blockIdx.y * 128;
    int m0 = (wid & 3) * 32, n0 = (wid >> 2) * 64;

    auto load_chunk = [&](int kc, int st) {
        uint32_t base = sb + (uint32_t)st * CHUNK;
        #pragma unroll
        for (int j = 0; j < 8; j++) {
            int idx = tid + j * 256;          // 0..2047
            int part = idx >> 9;              // 0..3
            int r = (idx >> 2) & 127, ch = idx & 3;
            uint32_t dst = base + (uint32_t)part * PART
                         + (uint32_t)(r * TS + ch * 8) * 2;
            // clamp A rows >= M to row M-1 (harmless: those acc rows unstored)
            int row = (part < 2) ? min(bm + r, M - 1) : (bn + r);
            const __nv_bfloat16* src =
                (part == 0) ? Ahi : (part == 1) ? Alo : (part == 2) ? Bhi : Blo;
            cp_async16(dst, src + row * 256 + kc * 32 + ch * 8);
        }
        CP_COMMIT();
    };

    float acc[2][8][4];
    #pragma unroll
    for (int i = 0; i < 2; i++)
        #pragma unroll
        for (int j = 0; j < 8; j++)
            #pragma unroll
            for (int q = 0; q < 4; q++) acc[i][j][q] = 0.0f;

    load_chunk(0, 0);
    load_chunk(1, 1);

    int a_row = lid & 15;
    int a_koff = ((lid >> 4) & 1) * 8;
    int b_n = (lid & 7) + ((lid >> 4) & 1) * 8;
    int b_koff = ((lid >> 3) & 1) * 8;

    for (int kc = 0; kc < 8; kc++) {
        int s = kc & 1;
        if (kc == 7) { CP_WAIT(0); } else { CP_WAIT(1); }
        __syncthreads();
        uint32_t ah_b = sb + (uint32_t)s * CHUNK;
        uint32_t al_b = ah_b + PART;
        uint32_t bh_b = al_b + PART;
        uint32_t bl_b = bh_b + PART;

        #pragma unroll
        for (int ks = 0; ks < 2; ks++) {
            int kcol = ks * 16 + a_koff;
            uint32_t ah[2][4], al[2][4];
            #pragma unroll
            for (int mf = 0; mf < 2; mf++) {
                uint32_t off = ((m0 + mf * 16 + a_row) * TS + kcol) * 2;
                ldsm_x4(ah[mf], ah_b + off);
                ldsm_x4(al[mf], al_b + off);
            }
            int kB = ks * 16 + b_koff;
            #pragma unroll
            for (int nf = 0; nf < 4; nf++) {
                uint32_t boff = ((n0 + nf * 16 + b_n) * TS + kB) * 2;
                uint32_t bh[4], bl[4];
                ldsm_x4(bh, bh_b + boff);     // no .trans: [n][k] is col-major B
                ldsm_x4(bl, bl_b + boff);
                #pragma unroll
                for (int mf = 0; mf < 2; mf++) {
                    mma_bf16(acc[mf][2 * nf],     ah[mf], bh[0], bh[1]);  // hi*hi
                    mma_bf16(acc[mf][2 * nf + 1], ah[mf], bh[2], bh[3]);
                    mma_bf16(acc[mf][2 * nf],     ah[mf], bl[0], bl[1]);  // hi*lo
                    mma_bf16(acc[mf][2 * nf + 1], ah[mf], bl[2], bl[3]);
                    mma_bf16(acc[mf][2 * nf],     al[mf], bh[0], bh[1]);  // lo*hi
                    mma_bf16(acc[mf][2 * nf + 1], al[mf], bh[2], bh[3]);
                }
            }
        }
        __syncthreads();                      // writers below touch stage s
        if (kc + 2 < 8) load_chunk(kc + 2, s);
    }

    int erow = lid >> 2, ecol = (lid & 3) * 2;
    #pragma unroll
    for (int mf = 0; mf < 2; mf++) {
        #pragma unroll
        for (int nf = 0; nf < 8; nf++) {
            int gr0 = bm + m0 + mf * 16 + erow;
            int gc = bn + n0 + nf * 8 + ecol;
            float v0 = acc[mf][nf][0], v1 = acc[mf][nf][1];
            float v2 = acc[mf][nf][2], v3 = acc[mf][nf][3];
            if (BR) {
                float b0 = bias[gc], b1 = bias[gc + 1];
                v0 = fmaxf(v0 + b0, 0.f); v1 = fmaxf(v1 + b1, 0.f);
                v2 = fmaxf(v2 + b0, 0.f); v3 = fmaxf(v3 + b1, 0.f);
            }
            if (gr0 < M)     *(float2*)&C[gr0 * 256 + gc]       = make_float2(v0, v1);
            if (gr0 + 8 < M) *(float2*)&C[(gr0 + 8) * 256 + gc] = make_float2(v2, v3);
        }
    }
}

// ---------------- pool (deterministic partials) + classifier --------------
__global__ void __launch_bounds__(256)
pool_partial_kernel(const float* __restrict__ h) {
    int g = blockIdx.x, j = blockIdx.y, t = threadIdx.x;   // grid (NG, 8)
    int s = g_gstart[g], e = g_gstart[g + 1];
    int len = e - s;
    int chunk = (len + 7) >> 3;
    int cs = s + j * chunk;
    int ce = min(cs + chunk, e);
    float a0 = 0.f, a1 = 0.f, a2 = 0.f, a3 = 0.f;
    int n = cs;
    for (; n + 4 <= ce; n += 4) {
        a0 += h[n * HD + t];
        a1 += h[(n + 1) * HD + t];
        a2 += h[(n + 2) * HD + t];
        a3 += h[(n + 3) * HD + t];
    }
    for (; n < ce; n++) a0 += h[n * HD + t];
    g_poolp[(g * 8 + j) * HD + t] = (a0 + a1) + (a2 + a3);
}
__global__ void __launch_bounds__(256)
classifier_kernel(const float* __restrict__ cW1, const float* __restrict__ cb1,
                  const float* __restrict__ cW2, const float* __restrict__ cb2,
                  float* __restrict__ out) {
    __shared__ float sp[HD];
    __shared__ float sz[128];
    int g = blockIdx.x, t = threadIdx.x;
    float c = (float)(g_gstart[g + 1] - g_gstart[g]);
    float s = 0.f;
    #pragma unroll
    for (int j = 0; j < 8; j++) s += g_poolp[(g * 8 + j) * HD + t];
    sp[t] = s / fmaxf(c, 1.0f);
    __syncthreads();
    if (t < 128) {
        float acc = cb1[t];
        #pragma unroll 4
        for (int k = 0; k < HD; k++) acc = fmaf(sp[k], cW1[k * 128 + t], acc);
        sz[t] = fmaxf(acc, 0.0f);
    }
    __syncthreads();
    if (t < 16) {
        float a = cb2[t];
        #pragma unroll 4
        for (int j = 0; j < 128; j++) a = fmaf(sz[j], cW2[j * 16 + t], a);
        out[g * 16 + t] = a;
    }
}

// ---------------- launch --------------------------------------------------
extern "C" void kernel_launch(void* const* d_in, const int* in_sizes, int n_in,
                              void* d_out, int out_size) {
    const void* p_x = 0; const void* p_ei = 0; const void* p_batch = 0;
    const void* p_W[3] = {0, 0, 0}; int nW = 0;
    const void* p_b[3] = {0, 0, 0}; int nb = 0;
    const void* p_cW1 = 0; const void* p_cb1 = 0;
    const void* p_cW2 = 0; const void* p_cb2 = 0;
    for (int i = 0; i < n_in; i++) {
        int sz = in_sizes[i]; const void* p = d_in[i];
        if      (sz == NN * HD)  p_x = p;
        else if (sz == 2 * EE)   p_ei = p;
        else if (sz == NN)       p_batch = p;
        else if (sz == HD * HD)  { if (nW < 3) p_W[nW++] = p; }
        else if (sz == HD)       { if (nb < 3) p_b[nb++] = p; }
        else if (sz == HD * 128) p_cW1 = p;
        else if (sz == 128)      p_cb1 = p;
        else if (sz == 128 * 16) p_cW2 = p;
        else if (sz == 16)       p_cb2 = p;
    }
    const float* x     = (const float*)p_x;
    const int*   ei    = (const int*)p_ei;
    const int*   batch = (const int*)p_batch;
    const float* b0 = (const float*)p_b[0];
    const float* b1 = (const float*)p_b[1];
    const float* b2 = (const float*)p_b[2];
    const float* cW1 = (const float*)p_cW1; const float* cb1 = (const float*)p_cb1;
    const float* cW2 = (const float*)p_cW2; const float* cb2 = (const float*)p_cb2;
    float* out = (float*)d_out;

    float* bufA; cudaGetSymbolAddress((void**)&bufA, g_bufA);
    float* bufB; cudaGetSymbolAddress((void**)&bufB, g_bufB);
    __nv_bfloat16* ahi; cudaGetSymbolAddress((void**)&ahi, g_ahi);
    __nv_bfloat16* alo; cudaGetSymbolAddress((void**)&alo, g_alo);
    __nv_bfloat16* wthi; cudaGetSymbolAddress((void**)&wthi, g_wthi);
    __nv_bfloat16* wtlo; cudaGetSymbolAddress((void**)&wtlo, g_wtlo);
    void* cntp;  cudaGetSymbolAddress(&cntp,  g_cnt);
    void* fillp; cudaGetSymbolAddress(&fillp, g_fill);
    void* bsump; cudaGetSymbolAddress(&bsump, g_bsum);

    cudaFuncSetAttribute(gemm_mma_kernel<false>,
                         cudaFuncAttributeMaxDynamicSharedMemorySize, GSMEM);
    cudaFuncSetAttribute(gemm_mma_kernel<true>,
                         cudaFuncAttributeMaxDynamicSharedMemorySize, GSMEM);

    static cudaStream_t s_side = 0;
    static cudaEvent_t  s_evRoot = 0, s_evJoin = 0;
    if (!s_side) {
        cudaStreamCreateWithFlags(&s_side, cudaStreamNonBlocking);
        cudaEventCreateWithFlags(&s_evRoot, cudaEventDisableTiming);
        cudaEventCreateWithFlags(&s_evJoin, cudaEventDisableTiming);
    }

    dim3 ggrid(MTILES, 2);
    int aggrid = (NN + 7) / 8;

    // ---- fork: CSR build on side stream ----
    cudaEventRecord(s_evRoot, 0);
    cudaStreamWaitEvent(s_side, s_evRoot, 0);
    cudaMemsetAsync(cntp,  0, NN * sizeof(int), s_side);
    cudaMemsetAsync(fillp, 0, NN * sizeof(int), s_side);
    cudaMemsetAsync(bsump, 0, 64 * sizeof(int), s_side);
    count_kernel<<<(EE + 255) / 256, 256, 0, s_side>>>(ei, batch);
    scan_kernel<<<NBLK, SCAN_B, 0, s_side>>>();
    fill_kernel<<<(EE + 255) / 256, 256, 0, s_side>>>(ei);
    cudaEventRecord(s_evJoin, s_side);

    // main: converts + layer-1 GEMM (independent of CSR)
    convert_w_kernel<<<(3 * HD * HD + 255) / 256, 256>>>(
        (const float*)p_W[0], (const float*)p_W[1], (const float*)p_W[2]);
    convert_x_kernel<<<(NN * HD / 4 + 255) / 256, 256>>>(x);
    gemm_mma_kernel<false><<<ggrid, 256, GSMEM>>>(ahi, alo, wthi, wtlo, 0, bufB, NN);

    // ---- join: agg needs CSR + GEMM output ----
    cudaStreamWaitEvent(0, s_evJoin, 0);
    // h1 = relu(Â t1 + b0)  (f32 out: agg2 gathers from it)
    agg_kernel<true, false><<<aggrid, 256>>>(bufB, b0, bufA);
    // layer 2: g2 = Â h1 (bf16 out) ; h2 = relu(g2 W1 + b1)
    agg_kernel<false, true><<<aggrid, 256>>>(bufA, 0, 0);
    gemm_mma_kernel<true><<<ggrid, 256, GSMEM>>>(ahi, alo, wthi + 65536, wtlo + 65536, b1, bufB, NN);
    // layer 3
    agg_kernel<false, true><<<aggrid, 256>>>(bufB, 0, 0);
    gemm_mma_kernel<true><<<ggrid, 256, GSMEM>>>(ahi, alo, wthi + 131072, wtlo + 131072, b2, bufA, NN);
    // pool + head
    pool_partial_kernel<<<dim3(NG, 8), 256>>>(bufA);
    classifier_kernel<<<NG, 256>>>(cW1, cb1, cW2, cb2, out);
}

// round 15
// speedup vs baseline: 1.0505x; 1.0505x over previous
#include <cuda_runtime.h>
#include <cuda_bf16.h>
#include <cstdint>

// ---------------- problem constants ----------------
#define NN   50000
#define EE   600000
#define HD   256
#define NG   64
#define SCAN_B 1024
#define NBLK ((NN + SCAN_B - 1) / SCAN_B)   // 49
#define MTILES ((NN + 127) / 128)           // 391

// ---------------- device scratch -------------------
__device__ float g_bufA[NN * HD];
__device__ float g_bufB[NN * HD];
__device__ __nv_bfloat16 g_wthi[3 * HD * HD];  // W^T split hi [layer][n][k]
__device__ __nv_bfloat16 g_wtlo[3 * HD * HD];  // W^T split lo
__device__ float g_dinv[NN];
__device__ int   g_rowptr[NN + 1];
__device__ int   g_cnt[NN];
__device__ int   g_fill[NN];
__device__ int2  g_edge[EE];                   // packed (col, val-as-int)
__device__ int   g_gstart[NG + 1];
__device__ int   g_bsum[64];
__device__ float g_poolp[NG * 8 * HD];         // partial pools

// ---------------- small helpers ----------------
__device__ __forceinline__ uint32_t smem_u32(const void* p) {
    uint32_t a;
    asm("{ .reg .u64 t; cvta.to.shared.u64 t, %1; cvt.u32.u64 %0, t; }"
        : "=r"(a) : "l"(p));
    return a;
}
__device__ __forceinline__ void cp_async16(uint32_t dst, const void* src) {
    asm volatile("cp.async.cg.shared.global [%0], [%1], 16;"
                 :: "r"(dst), "l"(src));
}
#define CP_COMMIT() asm volatile("cp.async.commit_group;")
#define CP_WAIT(n)  asm volatile("cp.async.wait_group %0;" :: "n"(n))

__device__ __forceinline__ void ldsm_x4(uint32_t* r, uint32_t addr) {
    asm volatile("ldmatrix.sync.aligned.m8n8.x4.shared.b16 {%0,%1,%2,%3}, [%4];"
                 : "=r"(r[0]), "=r"(r[1]), "=r"(r[2]), "=r"(r[3]) : "r"(addr));
}
__device__ __forceinline__ void mma_bf16(float* c, const uint32_t* a,
                                         uint32_t b0, uint32_t b1) {
    asm volatile(
        "mma.sync.aligned.m16n8k16.row.col.f32.bf16.bf16.f32 "
        "{%0,%1,%2,%3}, {%4,%5,%6,%7}, {%8,%9}, {%0,%1,%2,%3};"
        : "+f"(c[0]), "+f"(c[1]), "+f"(c[2]), "+f"(c[3])
        : "r"(a[0]), "r"(a[1]), "r"(a[2]), "r"(a[3]), "r"(b0), "r"(b1));
}
__device__ __forceinline__ void split_bf16(float v, __nv_bfloat16& hi, __nv_bfloat16& lo) {
    hi = __float2bfloat16(v);
    lo = __float2bfloat16(v - __bfloat162float(hi));
}

// ---------------- setup kernels ----------------
__global__ void count_kernel(const int* __restrict__ ei, const int* __restrict__ batch) {
    int e = blockIdx.x * blockDim.x + threadIdx.x;
    if (e < EE) {
        int d = ei[EE + e];
        atomicAdd(&g_cnt[d], 1);
        atomicAdd(&g_bsum[d >> 10], 1);
    }
    if (blockIdx.x == 0 && threadIdx.x <= NG) {
        int g = threadIdx.x;
        int lo = 0, hi = NN;
        while (lo < hi) { int m = (lo + hi) >> 1; if (batch[m] < g) lo = m + 1; else hi = m; }
        g_gstart[g] = lo;
    }
}
__global__ void scan_kernel() {
    __shared__ int sh[SCAN_B];
    __shared__ int sb[64];
    __shared__ int spref;
    int b = blockIdx.x, t = threadIdx.x;
    if (t < 64) sb[t] = (t < NBLK) ? g_bsum[t] : 0;
    __syncthreads();
    if (t == 0) {
        int s = 0;
        for (int i = 0; i < b; i++) s += sb[i];
        spref = s;
    }
    int i = b * SCAN_B + t;
    int c = (i < NN) ? g_cnt[i] : 0;
    if (i < NN) g_dinv[i] = rsqrtf((float)(c + 1));
    sh[t] = c;
    __syncthreads();
    #pragma unroll
    for (int off = 1; off < SCAN_B; off <<= 1) {
        int x = (t >= off) ? sh[t - off] : 0;
        __syncthreads();
        sh[t] += x;
        __syncthreads();
    }
    if (i < NN) g_rowptr[i + 1] = sh[t] + spref;
    if (b == 0 && t == 0) g_rowptr[0] = 0;
}
__global__ void fill_kernel(const int* __restrict__ ei) {
    int e = blockIdx.x * blockDim.x + threadIdx.x;
    if (e < EE) {
        int s = ei[e], d = ei[EE + e];
        int p = g_rowptr[d] + atomicAdd(&g_fill[d], 1);
        g_edge[p] = make_int2(s, __float_as_int(g_dinv[s]));
    }
}
// convert one weight matrix into Wt hi/lo at the given layer slot
__global__ void convert_w1_kernel(const float* __restrict__ W, int layer) {
    int i = blockIdx.x * blockDim.x + threadIdx.x;
    if (i >= HD * HD) return;
    int n = i / HD, k = i % HD;
    __nv_bfloat16 h, l; split_bf16(W[k * HD + n], h, l);   // Wt[n][k] = W[k][n]
    g_wthi[layer * HD * HD + i] = h;
    g_wtlo[layer * HD * HD + i] = l;
}
__global__ void convert_w2_kernel(const float* __restrict__ W1,
                                  const float* __restrict__ W2) {
    int i = blockIdx.x * blockDim.x + threadIdx.x;
    if (i >= 2 * HD * HD) return;
    int layer = 1 + i / (HD * HD), r = i % (HD * HD);
    int n = r / HD, k = r % HD;
    const float* W = (layer == 1) ? W1 : W2;
    __nv_bfloat16 h, l; split_bf16(W[k * HD + n], h, l);
    g_wthi[layer * HD * HD + r] = h;
    g_wtlo[layer * HD * HD + r] = l;
}

// ---------------- aggregation: g = D^-1/2 (A+I) D^-1/2 h ------------------
// warp per node, lane owns 8 features (2 x float4). BR: fuse +bias, relu.
template <bool BR>
__global__ void __launch_bounds__(256)
agg_kernel(const float* __restrict__ h, const float* __restrict__ bias,
           float* __restrict__ g) {
    int node = blockIdx.x * 8 + (threadIdx.x >> 5);
    if (node >= NN) return;
    int lane = threadIdx.x & 31;
    int fb = lane * 8;
    float di = g_dinv[node];
    float4 a0, a1;
    {
        const float4* hp = (const float4*)&h[node * HD + fb];
        float4 v0 = hp[0], v1 = hp[1];
        a0 = make_float4(di * v0.x, di * v0.y, di * v0.z, di * v0.w);
        a1 = make_float4(di * v1.x, di * v1.y, di * v1.z, di * v1.w);
    }
    int beg = g_rowptr[node], end = g_rowptr[node + 1];
    int p = beg;
    for (; p + 4 <= end; p += 4) {
        int2 e0 = g_edge[p],     e1 = g_edge[p + 1];
        int2 e2 = g_edge[p + 2], e3 = g_edge[p + 3];
        float w0 = __int_as_float(e0.y), w1 = __int_as_float(e1.y);
        float w2 = __int_as_float(e2.y), w3 = __int_as_float(e3.y);
        const float4* h0 = (const float4*)&h[e0.x * HD + fb];
        const float4* h1 = (const float4*)&h[e1.x * HD + fb];
        const float4* h2 = (const float4*)&h[e2.x * HD + fb];
        const float4* h3 = (const float4*)&h[e3.x * HD + fb];
        float4 u00 = h0[0], u01 = h0[1];
        float4 u10 = h1[0], u11 = h1[1];
        float4 u20 = h2[0], u21 = h2[1];
        float4 u30 = h3[0], u31 = h3[1];
        a0.x = fmaf(w0, u00.x, a0.x); a0.y = fmaf(w0, u00.y, a0.y);
        a0.z = fmaf(w0, u00.z, a0.z); a0.w = fmaf(w0, u00.w, a0.w);
        a1.x = fmaf(w0, u01.x, a1.x); a1.y = fmaf(w0, u01.y, a1.y);
        a1.z = fmaf(w0, u01.z, a1.z); a1.w = fmaf(w0, u01.w, a1.w);
        a0.x = fmaf(w1, u10.x, a0.x); a0.y = fmaf(w1, u10.y, a0.y);
        a0.z = fmaf(w1, u10.z, a0.z); a0.w = fmaf(w1, u10.w, a0.w);
        a1.x = fmaf(w1, u11.x, a1.x); a1.y = fmaf(w1, u11.y, a1.y);
        a1.z = fmaf(w1, u11.z, a1.z); a1.w = fmaf(w1, u11.w, a1.w);
        a0.x = fmaf(w2, u20.x, a0.x); a0.y = fmaf(w2, u20.y, a0.y);
        a0.z = fmaf(w2, u20.z, a0.z); a0.w = fmaf(w2, u20.w, a0.w);
        a1.x = fmaf(w2, u21.x, a1.x); a1.y = fmaf(w2, u21.y, a1.y);
        a1.z = fmaf(w2, u21.z, a1.z); a1.w = fmaf(w2, u21.w, a1.w);
        a0.x = fmaf(w3, u30.x, a0.x); a0.y = fmaf(w3, u30.y, a0.y);
        a0.z = fmaf(w3, u30.z, a0.z); a0.w = fmaf(w3, u30.w, a0.w);
        a1.x = fmaf(w3, u31.x, a1.x); a1.y = fmaf(w3, u31.y, a1.y);
        a1.z = fmaf(w3, u31.z, a1.z); a1.w = fmaf(w3, u31.w, a1.w);
    }
    for (; p < end; p++) {
        int2 e0 = g_edge[p];
        float w = __int_as_float(e0.y);
        const float4* hp = (const float4*)&h[e0.x * HD + fb];
        float4 u0 = hp[0], u1 = hp[1];
        a0.x = fmaf(w, u0.x, a0.x); a0.y = fmaf(w, u0.y, a0.y);
        a0.z = fmaf(w, u0.z, a0.z); a0.w = fmaf(w, u0.w, a0.w);
        a1.x = fmaf(w, u1.x, a1.x); a1.y = fmaf(w, u1.y, a1.y);
        a1.z = fmaf(w, u1.z, a1.z); a1.w = fmaf(w, u1.w, a1.w);
    }
    float4 r0 = make_float4(di * a0.x, di * a0.y, di * a0.z, di * a0.w);
    float4 r1 = make_float4(di * a1.x, di * a1.y, di * a1.z, di * a1.w);
    if (BR) {
        float4 b0v = *(const float4*)&bias[fb];
        float4 b1v = *(const float4*)&bias[fb + 4];
        r0 = make_float4(fmaxf(r0.x + b0v.x, 0.f), fmaxf(r0.y + b0v.y, 0.f),
                         fmaxf(r0.z + b0v.z, 0.f), fmaxf(r0.w + b0v.w, 0.f));
        r1 = make_float4(fmaxf(r1.x + b1v.x, 0.f), fmaxf(r1.y + b1v.y, 0.f),
                         fmaxf(r1.z + b1v.z, 0.f), fmaxf(r1.w + b1v.w, 0.f));
    }
    float4* gp = (float4*)&g[node * HD + fb];
    gp[0] = r0;
    gp[1] = r1;
}

// ---------------- mma.sync GEMM: C = [relu](A @ W [+ bias]) ---------------
// split-2 bf16 (A f32 -> hi/lo in regs, prefetched 1 iter ahead).
// CTA 128(M) x 256(N, FULL), 16 warps (4m x 4n), warp tile 32x64.
// K chunks of 32; B: 3-stage cp.async ring; A: 2-stage reg->smem.
// Same inner loop / sync discipline as the measured 70us kernel; A read ONCE.
#define TS     40
#define APART  (128 * TS * 2)         // 10240 B
#define BPART  (256 * TS * 2)         // 20480 B
#define A_OFF(s) ((uint32_t)((s) * 2 * APART))
#define B_OFF(s) ((uint32_t)(4 * APART + (s) * 2 * BPART))
#define GSMEM  (4 * APART + 3 * 2 * BPART)   // 163840 B

template <bool BR>
__global__ void __launch_bounds__(512, 1)
gemm_mma_kernel(const float* __restrict__ Af32,
                const __nv_bfloat16* __restrict__ Bhi,
                const __nv_bfloat16* __restrict__ Blo,
                const float* __restrict__ bias,
                float* __restrict__ C, int M) {
    extern __shared__ char smem[];
    uint32_t sb = smem_u32(smem);
    int tid = threadIdx.x, wid = tid >> 5, lid = tid & 31;
    int bm = blockIdx.x * 128;
    int m0 = (wid & 3) * 32, n0 = (wid >> 2) * 64;

    // A prefetch: 1 task/thread (row tid>>2, chunk col tid&3 -> 8 floats)
    int a_r = tid >> 2, a_ch = tid & 3;
    float4 pf[2];
    auto ldg_A = [&](int kc) {
        int gr = bm + a_r;
        if (gr < M) {
            const float* s0 = Af32 + gr * 256 + kc * 32 + a_ch * 8;
            pf[0] = *(const float4*)s0; pf[1] = *(const float4*)(s0 + 4);
        } else { pf[0] = make_float4(0, 0, 0, 0); pf[1] = pf[0]; }
    };
    auto sts_A = [&](int s) {
        uint32_t off = (uint32_t)(a_r * TS + a_ch * 8) * 2;
        union { __nv_bfloat16 v[8]; uint4 u; } H, L;
        float fv[8] = { pf[0].x, pf[0].y, pf[0].z, pf[0].w,
                        pf[1].x, pf[1].y, pf[1].z, pf[1].w };
        #pragma unroll
        for (int q = 0; q < 8; q++) split_bf16(fv[q], H.v[q], L.v[q]);
        *(uint4*)(smem + A_OFF(s) + off) = H.u;
        *(uint4*)(smem + A_OFF(s) + APART + off) = L.u;
    };
    auto cp_B = [&](int kc, int st) {
        uint32_t base = sb + B_OFF(st);
        #pragma unroll
        for (int j = 0; j < 4; j++) {
            int q = tid + j * 512;            // 0..2047
            int hl = q >> 10;                 // 0 hi, 1 lo
            int r = (q >> 2) & 255, ch = q & 3;
            uint32_t dst = base + (uint32_t)hl * BPART
                         + (uint32_t)(r * TS + ch * 8) * 2;
            const __nv_bfloat16* src = hl ? Blo : Bhi;
            cp_async16(dst, src + r * 256 + kc * 32 + ch * 8);
        }
        CP_COMMIT();
    };

    float acc[2][8][4];
    #pragma unroll
    for (int i = 0; i < 2; i++)
        #pragma unroll
        for (int j = 0; j < 8; j++)
            #pragma unroll
            for (int q = 0; q < 4; q++) acc[i][j][q] = 0.0f;

    // prologue (identical discipline to the measured kernel)
    cp_B(0, 0);
    cp_B(1, 1);
    ldg_A(0);
    sts_A(0);
    ldg_A(1);

    int a_row = lid & 15;
    int a_koff = ((lid >> 4) & 1) * 8;
    int b_n = (lid & 7) + ((lid >> 4) & 1) * 8;
    int b_koff = ((lid >> 3) & 1) * 8;

    int sB = 0, sB2 = 2;
    for (int kc = 0; kc < 8; kc++) {
        int s = kc & 1;
        if (kc == 7) { CP_WAIT(0); } else { CP_WAIT(1); }
        __syncthreads();
        uint32_t ah_b = sb + A_OFF(s), al_b = ah_b + APART;
        uint32_t bh_b = sb + B_OFF(sB), bl_b = bh_b + BPART;

        #pragma unroll
        for (int ks = 0; ks < 2; ks++) {
            int kcol = ks * 16 + a_koff;
            uint32_t ah[2][4], al[2][4];
            #pragma unroll
            for (int mf = 0; mf < 2; mf++) {
                uint32_t off = ((m0 + mf * 16 + a_row) * TS + kcol) * 2;
                ldsm_x4(ah[mf], ah_b + off);
                ldsm_x4(al[mf], al_b + off);
            }
            int kB = ks * 16 + b_koff;
            #pragma unroll
            for (int nf = 0; nf < 4; nf++) {
                uint32_t boff = ((n0 + nf * 16 + b_n) * TS + kB) * 2;
                uint32_t bh[4], bl[4];
                ldsm_x4(bh, bh_b + boff);     // no .trans: [n][k] is col-major B
                ldsm_x4(bl, bl_b + boff);
                #pragma unroll
                for (int mf = 0; mf < 2; mf++) {
                    mma_bf16(acc[mf][2 * nf],     ah[mf], bh[0], bh[1]);  // hi*hi
                    mma_bf16(acc[mf][2 * nf + 1], ah[mf], bh[2], bh[3]);
                    mma_bf16(acc[mf][2 * nf],     ah[mf], bl[0], bl[1]);  // hi*lo
                    mma_bf16(acc[mf][2 * nf + 1], ah[mf], bl[2], bl[3]);
                    mma_bf16(acc[mf][2 * nf],     al[mf], bh[0], bh[1]);  // lo*hi
                    mma_bf16(acc[mf][2 * nf + 1], al[mf], bh[2], bh[3]);
                }
            }
        }
        if (kc < 7) {
            sts_A(1 - s);                     // stage read last iter; all past sync
            if (kc < 6) {
                ldg_A(kc + 2);
                cp_B(kc + 2, sB2);            // stage last read in iter kc-1
            }
        }
        sB = (sB == 2) ? 0 : sB + 1;
        sB2 = (sB2 == 2) ? 0 : sB2 + 1;
    }

    int erow = lid >> 2, ecol = (lid & 3) * 2;
    #pragma unroll
    for (int mf = 0; mf < 2; mf++) {
        #pragma unroll
        for (int nf = 0; nf < 8; nf++) {
            int gr0 = bm + m0 + mf * 16 + erow;
            int gc = n0 + nf * 8 + ecol;
            float v0 = acc[mf][nf][0], v1 = acc[mf][nf][1];
            float v2 = acc[mf][nf][2], v3 = acc[mf][nf][3];
            if (BR) {
                float b0 = bias[gc], b1 = bias[gc + 1];
                v0 = fmaxf(v0 + b0, 0.f); v1 = fmaxf(v1 + b1, 0.f);
                v2 = fmaxf(v2 + b0, 0.f); v3 = fmaxf(v3 + b1, 0.f);
            }
            if (gr0 < M)     *(float2*)&C[gr0 * 256 + gc]       = make_float2(v0, v1);
            if (gr0 + 8 < M) *(float2*)&C[(gr0 + 8) * 256 + gc] = make_float2(v2, v3);
        }
    }
}

// ---------------- pool (deterministic partials) + classifier --------------
__global__ void __launch_bounds__(256)
pool_partial_kernel(const float* __restrict__ h) {
    int g = blockIdx.x, j = blockIdx.y, t = threadIdx.x;   // grid (NG, 8)
    int s = g_gstart[g], e = g_gstart[g + 1];
    int len = e - s;
    int chunk = (len + 7) >> 3;
    int cs = s + j * chunk;
    int ce = min(cs + chunk, e);
    float a0 = 0.f, a1 = 0.f, a2 = 0.f, a3 = 0.f;
    int n = cs;
    for (; n + 4 <= ce; n += 4) {
        a0 += h[n * HD + t];
        a1 += h[(n + 1) * HD + t];
        a2 += h[(n + 2) * HD + t];
        a3 += h[(n + 3) * HD + t];
    }
    for (; n < ce; n++) a0 += h[n * HD + t];
    g_poolp[(g * 8 + j) * HD + t] = (a0 + a1) + (a2 + a3);
}
__global__ void __launch_bounds__(256)
classifier_kernel(const float* __restrict__ cW1, const float* __restrict__ cb1,
                  const float* __restrict__ cW2, const float* __restrict__ cb2,
                  float* __restrict__ out) {
    __shared__ float sp[HD];
    __shared__ float sz[128];
    int g = blockIdx.x, t = threadIdx.x;
    float c = (float)(g_gstart[g + 1] - g_gstart[g]);
    float s = 0.f;
    #pragma unroll
    for (int j = 0; j < 8; j++) s += g_poolp[(g * 8 + j) * HD + t];
    sp[t] = s / fmaxf(c, 1.0f);
    __syncthreads();
    if (t < 128) {
        float acc = cb1[t];
        #pragma unroll 4
        for (int k = 0; k < HD; k++) acc = fmaf(sp[k], cW1[k * 128 + t], acc);
        sz[t] = fmaxf(acc, 0.0f);
    }
    __syncthreads();
    if (t < 16) {
        float a = cb2[t];
        #pragma unroll 4
        for (int j = 0; j < 128; j++) a = fmaf(sz[j], cW2[j * 16 + t], a);
        out[g * 16 + t] = a;
    }
}

// ---------------- launch --------------------------------------------------
extern "C" void kernel_launch(void* const* d_in, const int* in_sizes, int n_in,
                              void* d_out, int out_size) {
    const void* p_x = 0; const void* p_ei = 0; const void* p_batch = 0;
    const void* p_W[3] = {0, 0, 0}; int nW = 0;
    const void* p_b[3] = {0, 0, 0}; int nb = 0;
    const void* p_cW1 = 0; const void* p_cb1 = 0;
    const void* p_cW2 = 0; const void* p_cb2 = 0;
    for (int i = 0; i < n_in; i++) {
        int sz = in_sizes[i]; const void* p = d_in[i];
        if      (sz == NN * HD)  p_x = p;
        else if (sz == 2 * EE)   p_ei = p;
        else if (sz == NN)       p_batch = p;
        else if (sz == HD * HD)  { if (nW < 3) p_W[nW++] = p; }
        else if (sz == HD)       { if (nb < 3) p_b[nb++] = p; }
        else if (sz == HD * 128) p_cW1 = p;
        else if (sz == 128)      p_cb1 = p;
        else if (sz == 128 * 16) p_cW2 = p;
        else if (sz == 16)       p_cb2 = p;
    }
    const float* x     = (const float*)p_x;
    const int*   ei    = (const int*)p_ei;
    const int*   batch = (const int*)p_batch;
    const float* b0 = (const float*)p_b[0];
    const float* b1 = (const float*)p_b[1];
    const float* b2 = (const float*)p_b[2];
    const float* cW1 = (const float*)p_cW1; const float* cb1 = (const float*)p_cb1;
    const float* cW2 = (const float*)p_cW2; const float* cb2 = (const float*)p_cb2;
    float* out = (float*)d_out;

    float* bufA; cudaGetSymbolAddress((void**)&bufA, g_bufA);
    float* bufB; cudaGetSymbolAddress((void**)&bufB, g_bufB);
    __nv_bfloat16* wthi; cudaGetSymbolAddress((void**)&wthi, g_wthi);
    __nv_bfloat16* wtlo; cudaGetSymbolAddress((void**)&wtlo, g_wtlo);
    void* cntp;  cudaGetSymbolAddress(&cntp,  g_cnt);
    void* fillp; cudaGetSymbolAddress(&fillp, g_fill);
    void* bsump; cudaGetSymbolAddress(&bsump, g_bsum);

    cudaFuncSetAttribute(gemm_mma_kernel<false>,
                         cudaFuncAttributeMaxDynamicSharedMemorySize, GSMEM);
    cudaFuncSetAttribute(gemm_mma_kernel<true>,
                         cudaFuncAttributeMaxDynamicSharedMemorySize, GSMEM);

    static cudaStream_t s_side = 0;
    static cudaEvent_t  s_evRoot = 0, s_evJoin = 0;
    if (!s_side) {
        cudaStreamCreateWithFlags(&s_side, cudaStreamNonBlocking);
        cudaEventCreateWithFlags(&s_evRoot, cudaEventDisableTiming);
        cudaEventCreateWithFlags(&s_evJoin, cudaEventDisableTiming);
    }

    dim3 ggrid(MTILES, 1);
    int aggrid = (NN + 7) / 8;

    // ---- fork ----
    cudaEventRecord(s_evRoot, 0);
    cudaStreamWaitEvent(s_side, s_evRoot, 0);
    cudaMemsetAsync(cntp,  0, NN * sizeof(int), s_side);
    cudaMemsetAsync(fillp, 0, NN * sizeof(int), s_side);
    cudaMemsetAsync(bsump, 0, 64 * sizeof(int), s_side);

    // submission order: 3 launches before gemm1 so gemm1 is ncu slot 4
    convert_w1_kernel<<<(HD * HD + 255) / 256, 256>>>((const float*)p_W[0], 0); // 1 main
    count_kernel<<<(EE + 255) / 256, 256, 0, s_side>>>(ei, batch);              // 2 side
    scan_kernel<<<NBLK, SCAN_B, 0, s_side>>>();                                 // 3 side
    gemm_mma_kernel<false><<<ggrid, 512, GSMEM>>>(x, wthi, wtlo, 0, bufB, NN);  // 4 main (profiled)
    convert_w2_kernel<<<(2 * HD * HD + 255) / 256, 256, 0, s_side>>>(
        (const float*)p_W[1], (const float*)p_W[2]);                            // 5 side
    fill_kernel<<<(EE + 255) / 256, 256, 0, s_side>>>(ei);                      // 6 side
    cudaEventRecord(s_evJoin, s_side);

    // ---- join: agg needs CSR (+ W1/W2 converts done before gemm2) ----
    cudaStreamWaitEvent(0, s_evJoin, 0);
    agg_kernel<true><<<aggrid, 256>>>(bufB, b0, bufA);    // h1 = relu(Â t1 + b0)
    // layer 2
    agg_kernel<false><<<aggrid, 256>>>(bufA, 0, bufB);
    gemm_mma_kernel<true><<<ggrid, 512, GSMEM>>>(bufB, wthi + 65536, wtlo + 65536, b1, bufA, NN);
    // layer 3
    agg_kernel<false><<<aggrid, 256>>>(bufA, 0, bufB);
    gemm_mma_kernel<true><<<ggrid, 512, GSMEM>>>(bufB, wthi + 131072, wtlo + 131072, b2, bufA, NN);
    // pool + head
    pool_partial_kernel<<<dim3(NG, 8), 256>>>(bufA);
    classifier_kernel<<<NG, 256>>>(cW1, cb1, cW2, cb2, out);
}